// round 2
// baseline (speedup 1.0000x reference)
#include <cuda_runtime.h>
#include <cuda_bf16.h>
#include <math.h>

// Inputs (metadata order):
//   d_in[0] predictions  float32 [B*S]  (B=1941, S=16384)
//   d_in[1] actuals      float32 [B*S]
//   d_in[2] indexes      int32   [S]
//   d_in[3] starts       int32   [N_SERIES=30490]
// Output: float32 scalar  sqrt( sum_{j,i: j>=starts[indexes[i]]} (p[j,i]-a[j,i])^2 / count )

#define MAX_S 32768

__device__ int       g_starts[MAX_S];   // starts[indexes[i]] per series column
__device__ double    g_sum;
__device__ long long g_count;

// ---------------------------------------------------------------------------
// Kernel 1: gather per-column start, compute count analytically, zero g_sum.
// Single block -> trivially ordered with respect to the zeroing.
// ---------------------------------------------------------------------------
__global__ __launch_bounds__(1024)
void prep_kernel(const int* __restrict__ indexes,
                 const int* __restrict__ starts,
                 int S, int B)
{
    __shared__ long long sh[32];
    long long local = 0;
    for (int i = threadIdx.x; i < S; i += blockDim.x) {
        int s = starts[indexes[i]];
        g_starts[i] = s;
        int c = B - s;
        local += (c > 0) ? c : 0;
    }
    for (int off = 16; off > 0; off >>= 1)
        local += __shfl_down_sync(0xFFFFFFFF, local, off);
    int lane = threadIdx.x & 31, wid = threadIdx.x >> 5;
    if (lane == 0) sh[wid] = local;
    __syncthreads();
    if (wid == 0) {
        int nwarps = (blockDim.x + 31) >> 5;
        long long v = (lane < nwarps) ? sh[lane] : 0;
        for (int off = 16; off > 0; off >>= 1)
            v += __shfl_down_sync(0xFFFFFFFF, v, off);
        if (lane == 0) {
            g_count = v;
            g_sum   = 0.0;
        }
    }
}

// ---------------------------------------------------------------------------
// Kernel 2: masked sum of squared differences. float4 vectorized, grid-stride,
// one double atomicAdd per block. S % 4 == 0 so quads never cross rows.
// ---------------------------------------------------------------------------
__global__ __launch_bounds__(256)
void sumsq_kernel(const float4* __restrict__ p,
                  const float4* __restrict__ a,
                  int n4, int S4)
{
    __shared__ float sh[32];
    const int4* st4 = reinterpret_cast<const int4*>(g_starts);

    float local = 0.0f;
    int stride = gridDim.x * blockDim.x;
    for (int idx = blockIdx.x * blockDim.x + threadIdx.x; idx < n4; idx += stride) {
        int row = idx / S4;          // batch/time row j
        int c4  = idx - row * S4;    // column-quad index
        int4   st = st4[c4];
        float4 pv = p[idx];
        float4 av = a[idx];
        float d0 = pv.x - av.x;
        float d1 = pv.y - av.y;
        float d2 = pv.z - av.z;
        float d3 = pv.w - av.w;
        float s0 = (row >= st.x) ? d0 * d0 : 0.0f;
        float s1 = (row >= st.y) ? d1 * d1 : 0.0f;
        float s2 = (row >= st.z) ? d2 * d2 : 0.0f;
        float s3 = (row >= st.w) ? d3 * d3 : 0.0f;
        local += (s0 + s1) + (s2 + s3);
    }

    for (int off = 16; off > 0; off >>= 1)
        local += __shfl_down_sync(0xFFFFFFFF, local, off);
    int lane = threadIdx.x & 31, wid = threadIdx.x >> 5;
    if (lane == 0) sh[wid] = local;
    __syncthreads();
    if (wid == 0) {
        int nwarps = (blockDim.x + 31) >> 5;
        float v = (lane < nwarps) ? sh[lane] : 0.0f;
        for (int off = 16; off > 0; off >>= 1)
            v += __shfl_down_sync(0xFFFFFFFF, v, off);
        if (lane == 0)
            atomicAdd(&g_sum, (double)v);
    }
}

// Scalar tail (only launched if n % 4 != 0; with this dataset it never is).
__global__ void sumsq_tail_kernel(const float* __restrict__ p,
                                  const float* __restrict__ a,
                                  int n_start, int n, int S)
{
    int i = n_start + blockIdx.x * blockDim.x + threadIdx.x;
    if (i < n) {
        int row = i / S;
        int col = i - row * S;
        float d = p[i] - a[i];
        float v = (row >= g_starts[col]) ? d * d : 0.0f;
        if (v != 0.0f) atomicAdd(&g_sum, (double)v);
    }
}

// ---------------------------------------------------------------------------
// Kernel 3: finalize
// ---------------------------------------------------------------------------
__global__ void finalize_kernel(float* __restrict__ out)
{
    out[0] = (float)sqrt(g_sum / (double)g_count);
}

extern "C" void kernel_launch(void* const* d_in, const int* in_sizes, int n_in,
                              void* d_out, int out_size)
{
    const float* predictions = (const float*)d_in[0];
    const float* actuals     = (const float*)d_in[1];
    const int*   indexes     = (const int*)d_in[2];
    const int*   starts      = (const int*)d_in[3];
    float*       out         = (float*)d_out;

    int n = in_sizes[0];          // B * S
    int S = in_sizes[2];          // 16384
    int B = n / S;                // 1941

    prep_kernel<<<1, 1024>>>(indexes, starts, S, B);

    int n4 = n / 4;
    int S4 = S / 4;
    const int TPB    = 256;
    int       blocks = 1184;      // ~8 blocks/SM on 148 SMs
    int max_blocks = (n4 + TPB - 1) / TPB;
    if (blocks > max_blocks) blocks = max_blocks;
    sumsq_kernel<<<blocks, TPB>>>((const float4*)predictions,
                                  (const float4*)actuals, n4, S4);

    int rem = n - n4 * 4;
    if (rem > 0) {
        sumsq_tail_kernel<<<(rem + 255) / 256, 256>>>(predictions, actuals,
                                                      n4 * 4, n, S);
    }

    finalize_kernel<<<1, 1>>>(out);
}

// round 3
// speedup vs baseline: 1.2164x; 1.2164x over previous
#include <cuda_runtime.h>
#include <cuda_bf16.h>
#include <math.h>

// Inputs (metadata order):
//   d_in[0] predictions  float32 [B*S]  (B=1941, S=16384)
//   d_in[1] actuals      float32 [B*S]
//   d_in[2] indexes      int32   [S]
//   d_in[3] starts       int32   [N_SERIES=30490]
// Output: float32 scalar  sqrt( sum_{j,i: j>=starts[indexes[i]]} (p[j,i]-a[j,i])^2 / count )

#define MAX_S        32768
#define PREP_BLOCKS  128
#define MAX_BLOCKS   2048

__device__ int    g_starts[MAX_S];           // starts[indexes[i]] per column
__device__ long long g_count_part[PREP_BLOCKS];
__device__ double g_partials[MAX_BLOCKS];    // per-block sums from sumsq

// ---------------------------------------------------------------------------
// Kernel 1: parallel gather of per-column starts + per-block count partials.
// No cross-block ordering needed: later kernels are stream-ordered after us.
// ---------------------------------------------------------------------------
__global__ __launch_bounds__(256)
void prep_kernel(const int* __restrict__ indexes,
                 const int* __restrict__ starts,
                 int S, int B)
{
    __shared__ long long sh[8];
    long long local = 0;
    int stride = gridDim.x * blockDim.x;
    for (int i = blockIdx.x * blockDim.x + threadIdx.x; i < S; i += stride) {
        int s = starts[indexes[i]];
        g_starts[i] = s;
        int c = B - s;
        local += (c > 0) ? c : 0;
    }
    for (int off = 16; off > 0; off >>= 1)
        local += __shfl_down_sync(0xFFFFFFFF, local, off);
    int lane = threadIdx.x & 31, wid = threadIdx.x >> 5;
    if (lane == 0) sh[wid] = local;
    __syncthreads();
    if (wid == 0) {
        long long v = (lane < (blockDim.x >> 5)) ? sh[lane] : 0;
        for (int off = 16; off > 0; off >>= 1)
            v += __shfl_down_sync(0xFFFFFFFF, v, off);
        if (lane == 0) g_count_part[blockIdx.x] = v;
    }
}

// ---------------------------------------------------------------------------
// Kernel 2: masked sum of squared differences. float4 vectorized, grid-stride.
// Per-block partial written to g_partials (overwritten each replay — no reset,
// no atomics). S % 4 == 0 so quads never cross rows.
// ---------------------------------------------------------------------------
__global__ __launch_bounds__(256)
void sumsq_kernel(const float4* __restrict__ p,
                  const float4* __restrict__ a,
                  int n4, int S4)
{
    __shared__ float sh[8];
    const int4* st4 = reinterpret_cast<const int4*>(g_starts);

    float local = 0.0f;
    int stride = gridDim.x * blockDim.x;
    for (int idx = blockIdx.x * blockDim.x + threadIdx.x; idx < n4; idx += stride) {
        int row = idx / S4;          // time row j
        int c4  = idx - row * S4;    // column-quad index
        int4   st = st4[c4];
        float4 pv = p[idx];
        float4 av = a[idx];
        float d0 = pv.x - av.x;
        float d1 = pv.y - av.y;
        float d2 = pv.z - av.z;
        float d3 = pv.w - av.w;
        float s0 = (row >= st.x) ? d0 * d0 : 0.0f;
        float s1 = (row >= st.y) ? d1 * d1 : 0.0f;
        float s2 = (row >= st.z) ? d2 * d2 : 0.0f;
        float s3 = (row >= st.w) ? d3 * d3 : 0.0f;
        local += (s0 + s1) + (s2 + s3);
    }

    for (int off = 16; off > 0; off >>= 1)
        local += __shfl_down_sync(0xFFFFFFFF, local, off);
    int lane = threadIdx.x & 31, wid = threadIdx.x >> 5;
    if (lane == 0) sh[wid] = local;
    __syncthreads();
    if (wid == 0) {
        float v = (lane < (blockDim.x >> 5)) ? sh[lane] : 0.0f;
        for (int off = 16; off > 0; off >>= 1)
            v += __shfl_down_sync(0xFFFFFFFF, v, off);
        if (lane == 0) g_partials[blockIdx.x] = (double)v;
    }
}

// ---------------------------------------------------------------------------
// Kernel 3: reduce partials + counts, write sqrt(sum/count). One block.
// ---------------------------------------------------------------------------
__global__ __launch_bounds__(1024)
void finalize_kernel(float* __restrict__ out, int n_blocks)
{
    __shared__ double shs[32];
    __shared__ long long shc[32];

    double    s = 0.0;
    long long c = 0;
    for (int i = threadIdx.x; i < n_blocks; i += blockDim.x)
        s += g_partials[i];
    for (int i = threadIdx.x; i < PREP_BLOCKS; i += blockDim.x)
        c += g_count_part[i];

    for (int off = 16; off > 0; off >>= 1) {
        s += __shfl_down_sync(0xFFFFFFFF, s, off);
        c += __shfl_down_sync(0xFFFFFFFF, c, off);
    }
    int lane = threadIdx.x & 31, wid = threadIdx.x >> 5;
    if (lane == 0) { shs[wid] = s; shc[wid] = c; }
    __syncthreads();
    if (wid == 0) {
        int nwarps = blockDim.x >> 5;
        double    vs = (lane < nwarps) ? shs[lane] : 0.0;
        long long vc = (lane < nwarps) ? shc[lane] : 0;
        for (int off = 16; off > 0; off >>= 1) {
            vs += __shfl_down_sync(0xFFFFFFFF, vs, off);
            vc += __shfl_down_sync(0xFFFFFFFF, vc, off);
        }
        if (lane == 0)
            out[0] = (float)sqrt(vs / (double)vc);
    }
}

extern "C" void kernel_launch(void* const* d_in, const int* in_sizes, int n_in,
                              void* d_out, int out_size)
{
    const float* predictions = (const float*)d_in[0];
    const float* actuals     = (const float*)d_in[1];
    const int*   indexes     = (const int*)d_in[2];
    const int*   starts      = (const int*)d_in[3];
    float*       out         = (float*)d_out;

    int n = in_sizes[0];          // B * S
    int S = in_sizes[2];          // 16384
    int B = n / S;                // 1941

    prep_kernel<<<PREP_BLOCKS, 256>>>(indexes, starts, S, B);

    int n4 = n / 4;
    int S4 = S / 4;
    const int TPB    = 256;
    int       blocks = 1184;      // ~8 blocks/SM
    int max_blocks = (n4 + TPB - 1) / TPB;
    if (blocks > max_blocks) blocks = max_blocks;
    if (blocks > MAX_BLOCKS)  blocks = MAX_BLOCKS;
    sumsq_kernel<<<blocks, TPB>>>((const float4*)predictions,
                                  (const float4*)actuals, n4, S4);

    finalize_kernel<<<1, 1024>>>(out, blocks);
}